// round 10
// baseline (speedup 1.0000x reference)
#include <cuda_runtime.h>
#include <cstdint>

#define N_NODES 10000
#define N_EDGES 640000
#define D_FEAT  128
#define EPS     1e-12f
#define CAP     192   // ELL capacity per node; deg ~ Poisson(64), P(>192) ~ 1e-20

// ---- scratch (allocation-free rule: __device__ globals) ----
// NOTE: zero-initialized at module load. k_spmm restores g_cursor to all-zero
// at the end of every pipeline run, so no separate init kernel is needed and
// every invocation (correctness run + each graph replay) is identical.
__device__ int  g_cursor[N_NODES];          // per-node fill count
__device__ int2 g_ell[N_NODES * CAP];       // (src, float-bits of ew) per slot

__device__ __forceinline__ void put(int t, int s, float w) {
    if ((unsigned)t >= (unsigned)N_NODES) t = 0;
    if ((unsigned)s >= (unsigned)N_NODES) s = 0;
    int p = atomicAdd(&g_cursor[t], 1);
    if (p < CAP) g_ell[t * CAP + p] = make_int2(s, (int)__float_as_uint(w));
}

// ---------------------------------------------------------------------------
// K1: scatter edges into ELL buckets. 8 edges per thread.
// Degree normalization cancels under ReLU + row-L2-normalize, so raw edge
// weights are stored and no degree pass exists.
// Edge dtype (int32 vs int64 delivery) is probed per-block from the data the
// block already loads: under int64 (ids < 2^31) every odd 32-bit word is 0.
__global__ __launch_bounds__(256) void k_scatter(const void* __restrict__ edge,
                                                 const float* __restrict__ ew) {
    const int q  = blockIdx.x * blockDim.x + threadIdx.x;   // 8 edges / thread
    const int e0 = q * 8;
    const bool active = (e0 < N_EDGES);

    const int* __restrict__ e32 = (const int*)edge;
    int4 s0, s1, t0, t1;
    float4 w0, w1;
    if (active) {
        s0 = ((const int4*)e32)[q * 2];
        s1 = ((const int4*)e32)[q * 2 + 1];
        t0 = ((const int4*)(e32 + 2 * N_EDGES))[q * 2];
        t1 = ((const int4*)(e32 + 2 * N_EDGES))[q * 2 + 1];
        w0 = ((const float4*)ew)[q * 2];
        w1 = ((const float4*)ew)[q * 2 + 1];
    }
    int ok = active ? (s0.y == 0 && s0.w == 0 && s1.y == 0 && s1.w == 0) : 1;
    int is64 = __syncthreads_and(ok);   // block-uniform layout decision

    if (!active) return;

    if (!is64) {
        put(t0.x, s0.x, w0.x);
        put(t0.y, s0.y, w0.y);
        put(t0.z, s0.z, w0.z);
        put(t0.w, s0.w, w0.w);
        put(t1.x, s1.x, w1.x);
        put(t1.y, s1.y, w1.y);
        put(t1.z, s1.z, w1.z);
        put(t1.w, s1.w, w1.w);
    } else {
        const long long* e64 = (const long long*)edge;
#pragma unroll
        for (int k = 0; k < 8; k++) {
            int e = e0 + k;
            put((int)e64[2 * N_EDGES + e], (int)e64[e], ew[e]);
        }
    }
}

// ---------------------------------------------------------------------------
// K2: SpMM + ReLU + row L2-normalize. One warp per node row.
// Lane owns 4 consecutive features (float4): 32 lanes x 16B = 512B row.
// Self-cleaning: resets this row's cursor to 0 for the next invocation.
__global__ __launch_bounds__(256) void k_spmm(const float* __restrict__ x,
                                              float* __restrict__ out) {
    const int lane = threadIdx.x & 31;
    const int row  = (blockIdx.x * (blockDim.x >> 5)) + (threadIdx.x >> 5);
    if (row >= N_NODES) return;

    int cnt = g_cursor[row];
    if (lane == 0) g_cursor[row] = 0;      // restore invariant for next run
    if (cnt > CAP) cnt = CAP;
    const int2* __restrict__ ell = g_ell + row * CAP;

    const float4* __restrict__ x4 = (const float4*)x;
    float4 acc = make_float4(0.f, 0.f, 0.f, 0.f);

    for (int base = 0; base < cnt; base += 32) {
        int idx = base + lane;
        int2 ev = (idx < cnt) ? ell[idx] : make_int2(0, 0);
        int m = cnt - base; if (m > 32) m = 32;
#pragma unroll 4
        for (int k = 0; k < m; k++) {
            int   s  = __shfl_sync(0xffffffffu, ev.x, k);
            float wv = __uint_as_float((unsigned)__shfl_sync(0xffffffffu, ev.y, k));
            float4 v = x4[s * 32 + lane];
            acc.x += wv * v.x;
            acc.y += wv * v.y;
            acc.z += wv * v.z;
            acc.w += wv * v.w;
        }
    }

    // ReLU
    acc.x = fmaxf(acc.x, 0.f);
    acc.y = fmaxf(acc.y, 0.f);
    acc.z = fmaxf(acc.z, 0.f);
    acc.w = fmaxf(acc.w, 0.f);

    // row L2 norm via warp reduction (degree factor cancels here)
    float ss = acc.x * acc.x + acc.y * acc.y + acc.z * acc.z + acc.w * acc.w;
#pragma unroll
    for (int off = 16; off > 0; off >>= 1)
        ss += __shfl_xor_sync(0xffffffffu, ss, off);

    float inv = 1.0f / fmaxf(sqrtf(ss), EPS);
    float4 o;
    o.x = acc.x * inv; o.y = acc.y * inv; o.z = acc.z * inv; o.w = acc.w * inv;
    ((float4*)out)[row * 32 + lane] = o;
}

// ---------------------------------------------------------------------------
extern "C" void kernel_launch(void* const* d_in, const int* in_sizes, int n_in,
                              void* d_out, int out_size) {
    // Bind inputs by element count (robust to metadata ordering)
    const float* x    = nullptr;
    const void*  edge = nullptr;
    const float* ew   = nullptr;
    for (int i = 0; i < n_in; i++) {
        int sz = in_sizes[i];
        if (sz == N_NODES * D_FEAT)                       x    = (const float*)d_in[i];
        else if (sz == 3 * N_EDGES || sz == 6 * N_EDGES)  edge = d_in[i];
        else if (sz == N_EDGES)                           ew   = (const float*)d_in[i];
    }
    if (!x)    x    = (const float*)d_in[0];
    if (!edge) edge = d_in[1];
    if (!ew)   ew   = (const float*)d_in[2];
    float* out = (float*)d_out;

    // 640000 edges / 8 per thread = 80000 threads
    k_scatter<<<(N_EDGES / 8 + 255) / 256, 256>>>(edge, ew);
    int warpsPerBlock = 8;
    int blocks = (N_NODES + warpsPerBlock - 1) / warpsPerBlock;
    k_spmm<<<blocks, warpsPerBlock * 32>>>(x, out);
}

// round 14
// speedup vs baseline: 1.1651x; 1.1651x over previous
#include <cuda_runtime.h>
#include <cstdint>

#define N_NODES 10000
#define N_EDGES 640000
#define D_FEAT  128
#define EPS     1e-12f
#define CAP     192   // ELL capacity per node; deg ~ Poisson(64), P(>192) ~ 1e-20

// ---- scratch (allocation-free rule: __device__ globals) ----
// Zero-initialized at module load. k_spmm restores g_cursor to all-zero each
// run, so every invocation (correctness run + each graph replay) is identical.
__device__ int  g_cursor[N_NODES];          // per-node fill count
__device__ int2 g_ell[N_NODES * CAP];       // (src, float-bits of ew) per slot

__device__ __forceinline__ void put(int t, int s, float w) {
    if ((unsigned)t >= (unsigned)N_NODES) t = 0;
    if ((unsigned)s >= (unsigned)N_NODES) s = 0;
    int p = atomicAdd(&g_cursor[t], 1);
    if (p < CAP) g_ell[t * CAP + p] = make_int2(s, (int)__float_as_uint(w));
}

// ---------------------------------------------------------------------------
// K1: scatter edges into ELL buckets. 4 edges per thread, 625 full blocks.
// Degree normalization cancels under ReLU + row-L2-normalize, so raw weights
// are stored. Edge dtype (int32 vs int64 delivery) probed per-block from data
// the block already loads: int64 ids < 2^31 => every odd 32-bit word is 0.
__global__ __launch_bounds__(256) void k_scatter(const void* __restrict__ edge,
                                                 const float* __restrict__ ew) {
    const int q  = blockIdx.x * blockDim.x + threadIdx.x;   // 4 edges / thread
    const int e0 = q * 4;                                   // grid sized exactly

    const int* __restrict__ e32 = (const int*)edge;
    int4   s4 = ((const int4*)e32)[q];
    int4   t4 = ((const int4*)(e32 + 2 * N_EDGES))[q];
    float4 w4 = ((const float4*)ew)[q];

    int ok   = (s4.y == 0 && s4.w == 0);
    int is64 = __syncthreads_and(ok);   // block-uniform layout decision

    if (!is64) {
        put(t4.x, s4.x, w4.x);
        put(t4.y, s4.y, w4.y);
        put(t4.z, s4.z, w4.z);
        put(t4.w, s4.w, w4.w);
    } else {
        const long long* e64 = (const long long*)edge;
#pragma unroll
        for (int k = 0; k < 4; k++) {
            int e = e0 + k;
            put((int)e64[2 * N_EDGES + e], (int)e64[e], ew[e]);
        }
    }
}

// ---------------------------------------------------------------------------
// K2: SpMM + ReLU + row L2-normalize.
// Block = 256 threads = 2 rows x 4 warps/row. Each warp accumulates a
// contiguous quarter of the row's edges (float4 per lane = 512B row), then
// partials combine through shared memory. 4x the independent memory streams
// of the 1-warp/row version -> hides L2 gather latency.
// RACE FIX vs R11: all warps read g_cursor[row] BEFORE the barrier; the reset
// happens after it, so no warp can observe a zeroed count.
__global__ __launch_bounds__(256) void k_spmm(const float* __restrict__ x,
                                              float* __restrict__ out) {
    __shared__ float4 sm[8][32];
    const int lane = threadIdx.x & 31;
    const int wid  = threadIdx.x >> 5;   // 0..7
    const int grp  = wid >> 2;           // row within block (0..1)
    const int sub  = wid & 3;            // warp within row group
    const int row  = blockIdx.x * 2 + grp;   // grid = N_NODES/2, always valid

    int cnt = g_cursor[row];
    __syncthreads();                     // everyone has read cnt
    if (sub == 0 && lane == 0) g_cursor[row] = 0;   // restore invariant
    if (cnt > CAP) cnt = CAP;

    // this warp's contiguous edge range
    const int chunk = (cnt + 3) >> 2;
    const int lo = sub * chunk;
    const int hi = min(lo + chunk, cnt);

    const int2*   __restrict__ ell = g_ell + row * CAP;
    const float4* __restrict__ x4  = (const float4*)x;
    float4 acc = make_float4(0.f, 0.f, 0.f, 0.f);

    for (int base = lo; base < hi; base += 32) {
        int idx = base + lane;
        int2 ev = (idx < hi) ? ell[idx] : make_int2(0, 0);
        int m = hi - base; if (m > 32) m = 32;
#pragma unroll 8
        for (int k = 0; k < m; k++) {
            int   s  = __shfl_sync(0xffffffffu, ev.x, k);
            float wv = __uint_as_float((unsigned)__shfl_sync(0xffffffffu, ev.y, k));
            float4 v = __ldg(&x4[s * 32 + lane]);
            acc.x += wv * v.x;
            acc.y += wv * v.y;
            acc.z += wv * v.z;
            acc.w += wv * v.w;
        }
    }

    sm[wid][lane] = acc;
    __syncthreads();

    if (sub == 0) {
        float4 a = acc;
#pragma unroll
        for (int j = 1; j < 4; j++) {
            float4 b = sm[wid + j][lane];
            a.x += b.x; a.y += b.y; a.z += b.z; a.w += b.w;
        }

        // ReLU
        a.x = fmaxf(a.x, 0.f);
        a.y = fmaxf(a.y, 0.f);
        a.z = fmaxf(a.z, 0.f);
        a.w = fmaxf(a.w, 0.f);

        // row L2 norm via warp reduction (degree factor cancels here)
        float ss = a.x * a.x + a.y * a.y + a.z * a.z + a.w * a.w;
#pragma unroll
        for (int off = 16; off > 0; off >>= 1)
            ss += __shfl_xor_sync(0xffffffffu, ss, off);

        float inv = 1.0f / fmaxf(sqrtf(ss), EPS);
        float4 o;
        o.x = a.x * inv; o.y = a.y * inv; o.z = a.z * inv; o.w = a.w * inv;
        ((float4*)out)[row * 32 + lane] = o;
    }
}

// ---------------------------------------------------------------------------
extern "C" void kernel_launch(void* const* d_in, const int* in_sizes, int n_in,
                              void* d_out, int out_size) {
    // Bind inputs by element count (robust to metadata ordering)
    const float* x    = nullptr;
    const void*  edge = nullptr;
    const float* ew   = nullptr;
    for (int i = 0; i < n_in; i++) {
        int sz = in_sizes[i];
        if (sz == N_NODES * D_FEAT)                       x    = (const float*)d_in[i];
        else if (sz == 3 * N_EDGES || sz == 6 * N_EDGES)  edge = d_in[i];
        else if (sz == N_EDGES)                           ew   = (const float*)d_in[i];
    }
    if (!x)    x    = (const float*)d_in[0];
    if (!edge) edge = d_in[1];
    if (!ew)   ew   = (const float*)d_in[2];
    float* out = (float*)d_out;

    k_scatter<<<N_EDGES / 4 / 256, 256>>>(edge, ew);   // 625 full blocks
    k_spmm<<<N_NODES / 2, 256>>>(x, out);              // 5000 full blocks
}